// round 16
// baseline (speedup 1.0000x reference)
#include <cuda_runtime.h>
#include <math.h>

#define W   512
#define B   32
#define C   3
#define LIM 0.03125f                     // PIX_W * EPS = (2/512)*8
#define DEF_OFF_F (1.0f + 2.0f/511.0f)   // (2 + 4/511)/2
#define FULL 0xffffffffu

// ---------------- scratch (static device arrays; no runtime allocs) --------
__device__ float d_px[(size_t)B * W * W];         // sample x coord in pixels
__device__ float d_py[(size_t)B * W * W];         // sample y coord in pixels

__device__ __forceinline__ int refl(int i) {
    return i < 0 ? -i : (i >= W ? 2 * W - 2 - i : i);
}

// ==== merged scan kernel =====================================================
// blockIdx.z == 0 : x-channel row scan (16 rows/block, warp per row)
// blockIdx.z == 1 : y-channel column scan (32 cols/block, two-pass, low regs)
// 512 threads, 64KB dynamic smem for both roles.
#define XROWS 16
#define SEG 32
#define NSEG (W / SEG)

__global__ void k_scan(const float* __restrict__ pg,
                       float w0, float w1, float w2) {
    extern __shared__ float sm[];
    __shared__ float segsum[NSEG][33];
    int tid = threadIdx.x;               // 0..511
    int b = blockIdx.y;

    if (blockIdx.z == 0) {
        // ------------------- row role: blur(ch0) + row scan -----------------
        float (*ssrc)[W] = (float(*)[W])sm;             // [XROWS+4][W] = 40KB
        int y0 = blockIdx.x * XROWS;
        const float* src = pg + (size_t)(b * 2) * W * W;   // channel 0

        // load XROWS+4 source rows (vertical reflect), float4
        for (int i = tid; i < (XROWS + 4) * (W / 4); i += 512) {
            int r = i >> 7, c4 = i & 127;
            ((float4*)ssrc[r])[c4] =
                ((const float4*)(src + (size_t)refl(y0 + r - 2) * W))[c4];
        }
        __syncthreads();

        int warp = tid >> 5, lane = tid & 31;
        int y = y0 + warp;

        // vertical blur into registers (reads rows warp..warp+4)
        float v[16];
        #pragma unroll
        for (int k = 0; k < 16; k++) {
            int x = k * 32 + lane;
            v[k] = w0 * (ssrc[warp][x] + ssrc[warp + 4][x])
                 + w1 * (ssrc[warp + 1][x] + ssrc[warp + 3][x])
                 + w2 * ssrc[warp + 2][x];
        }
        __syncthreads();
        // write vblur in place (rows 0..15 now hold vblur of y0..y0+15)
        #pragma unroll
        for (int k = 0; k < 16; k++)
            ssrc[warp][k * 32 + lane] = v[k];
        __syncthreads();

        // horizontal blur + diff -> relu -> inclusive scan
        float last31 = 0.f;
        float run = 0.f;
        float* pxo = d_px + ((size_t)b * W + y) * W;
        #pragma unroll
        for (int k = 0; k < 16; k++) {
            int x = k * 32 + lane;
            int xm2 = (k == 0)  ? refl(x - 2) : x - 2;
            int xm1 = (k == 0)  ? refl(x - 1) : x - 1;
            int xp1 = (k == 15) ? refl(x + 1) : x + 1;
            int xp2 = (k == 15) ? refl(x + 2) : x + 2;
            float bl = w0 * (ssrc[warp][xm2] + ssrc[warp][xp2])
                     + w1 * (ssrc[warp][xm1] + ssrc[warp][xp1])
                     + w2 * ssrc[warp][x];
            float iden = (2.0f * x - (float)(W - 1)) * (1.0f / (W - 1));
            float s = bl + iden + DEF_OFF_F;
            float sprev = __shfl_up_sync(FULL, s, 1);
            if (lane == 0) sprev = last31;
            float a = fmaxf(s - sprev, 0.f);
            last31 = __shfl_sync(FULL, s, 31);

            float vv = a;
            #pragma unroll
            for (int o = 1; o < 32; o <<= 1) {
                float n = __shfl_up_sync(FULL, vv, o);
                if (lane >= o) vv += n;
            }
            float sx2 = run + vv;
            run += __shfl_sync(FULL, vv, 31);

            float pgv = sx2 - DEF_OFF_F - iden;
            pgv = fminf(fmaxf(pgv, -LIM), LIM);
            float gx = fminf(fmaxf(pgv + iden, -1.f), 1.f);
            pxo[x] = (gx + 1.f) * 0.5f * (float)(W - 1);
        }
    } else {
        // ------------------- col role: blur(ch1) + column scan --------------
        if (blockIdx.x >= W / 32) return;             // only 16 tiles needed
        float* hb = sm;                               // [W][32] = 64KB
        int tx = tid & 31;                            // column in tile
        int ty = tid >> 5;                            // segment 0..15
        int x = blockIdx.x * 32 + tx;
        const float* src = pg + (size_t)(b * 2 + 1) * W * W;   // channel 1

        int xm2 = refl(x - 2), xm1 = refl(x - 1);
        int xp1 = refl(x + 1), xp2 = refl(x + 2);

        // phase 1: horizontal blur, rows ty*32 .. ty*32+31
        int y0 = ty * SEG;
        #pragma unroll 4
        for (int r = 0; r < SEG; r++) {
            const float* row = src + (size_t)(y0 + r) * W;
            hb[(y0 + r) * 32 + tx] =
                w0 * (__ldg(row + xm2) + __ldg(row + xp2))
              + w1 * (__ldg(row + xm1) + __ldg(row + xp1))
              + w2 * __ldg(row + x);
        }
        __syncthreads();

        // pass A: segment sums only (no per-row values kept -> low regs)
        float h0 = hb[refl(y0 - 2) * 32 + tx];
        float h1 = hb[refl(y0 - 1) * 32 + tx];
        float h2 = hb[y0 * 32 + tx];
        float h3 = hb[(y0 + 1) * 32 + tx];
        float h4 = hb[refl(y0 + 2) * 32 + tx];

        float prev0 = 0.f;
        if (ty > 0) {   // s at row y0-1
            float g0 = hb[refl(y0 - 3) * 32 + tx];
            float vbp = w0 * (g0 + h3) + w1 * (h0 + h2) + w2 * h1;
            float idenp = (2.0f * (y0 - 1) - (float)(W - 1)) * (1.0f / (W - 1));
            prev0 = vbp + idenp + DEF_OFF_F;
        }

        float prev = prev0;
        float run = 0.f;
        {
            float g0 = h0, g1 = h1, g2 = h2, g3 = h3, g4 = h4;
            #pragma unroll
            for (int r = 0; r < SEG; r++) {
                int y = y0 + r;
                float vb = w0 * (g0 + g4) + w1 * (g1 + g3) + w2 * g2;
                float iden = (2.0f * y - (float)(W - 1)) * (1.0f / (W - 1));
                float s = vb + iden + DEF_OFF_F;
                run += fmaxf(s - prev, 0.f);
                prev = s;
                g0 = g1; g1 = g2; g2 = g3; g3 = g4;
                g4 = hb[refl(y + 3) * 32 + tx];
            }
        }
        segsum[ty][tx] = run;
        __syncthreads();

        if (ty == 0) {   // exclusive prefix over segments
            float off = 0.f;
            #pragma unroll
            for (int k = 0; k < NSEG; k++) {
                float t = segsum[k][tx];
                segsum[k][tx] = off;
                off += t;
            }
        }
        __syncthreads();
        float offset = segsum[ty][tx];

        // pass B: recompute scan from intact hb, write py
        prev = prev0;
        run = offset;
        float* py = d_py + (size_t)b * W * W + x;
        #pragma unroll
        for (int r = 0; r < SEG; r++) {
            int y = y0 + r;
            float vb = w0 * (h0 + h4) + w1 * (h1 + h3) + w2 * h2;
            float iden = (2.0f * y - (float)(W - 1)) * (1.0f / (W - 1));
            float s = vb + iden + DEF_OFF_F;
            run += fmaxf(s - prev, 0.f);
            prev = s;
            float pgv = run - DEF_OFF_F - iden;
            pgv = fminf(fmaxf(pgv, -LIM), LIM);
            float gy = fminf(fmaxf(pgv + iden, -1.f), 1.f);
            py[(size_t)y * W] = (gy + 1.f) * 0.5f * (float)(W - 1);
            h0 = h1; h1 = h2; h2 = h3; h3 = h4;
            h4 = hb[refl(y + 3) * 32 + tx];
        }
    }
}

// ==== bilinear grid sample, 4 pixels / thread ================================
// Grid coords are clipped to [-1,1] upstream => fx,fy in [0,511]:
// no validity predicates needed; only x1/y1 clamp (their weight is 0 there).
__device__ __forceinline__ void samp1(const float* __restrict__ ib,
                                      float fx, float fy,
                                      float& r0, float& r1, float& r2) {
    float x0f = floorf(fx), y0f = floorf(fy);
    int x0 = (int)x0f, y0 = (int)y0f;           // in [0,511]
    int x1 = min(x0 + 1, W - 1), y1 = min(y0 + 1, W - 1);
    float wx1 = fx - x0f, wx0 = 1.f - wx1;
    float wy1 = fy - y0f, wy0 = 1.f - wy1;

    float w00 = wx0 * wy0, w10 = wx1 * wy0;
    float w01 = wx0 * wy1, w11 = wx1 * wy1;

    size_t o00 = (size_t)y0 * W + x0, o10 = (size_t)y0 * W + x1;
    size_t o01 = (size_t)y1 * W + x0, o11 = (size_t)y1 * W + x1;
    r0 = w00 * __ldg(ib + o00) + w10 * __ldg(ib + o10)
       + w01 * __ldg(ib + o01) + w11 * __ldg(ib + o11);
    const float* i1 = ib + (size_t)W * W;
    r1 = w00 * __ldg(i1 + o00) + w10 * __ldg(i1 + o10)
       + w01 * __ldg(i1 + o01) + w11 * __ldg(i1 + o11);
    const float* i2 = ib + (size_t)2 * W * W;
    r2 = w00 * __ldg(i2 + o00) + w10 * __ldg(i2 + o10)
       + w01 * __ldg(i2 + o01) + w11 * __ldg(i2 + o11);
}

__global__ void k_sample(const float* __restrict__ img, float* __restrict__ out) {
    int t = blockIdx.x * blockDim.x + threadIdx.x;     // quad index
    if (t >= B * W * W / 4) return;
    int y = (t >> 7) & 511, b = t >> 16;

    float4 fx4 = ((const float4*)d_px)[t];
    float4 fy4 = ((const float4*)d_py)[t];

    const float* ib = img + (size_t)b * C * W * W;
    float4 c0, c1, c2;
    samp1(ib, fx4.x, fy4.x, c0.x, c1.x, c2.x);
    samp1(ib, fx4.y, fy4.y, c0.y, c1.y, c2.y);
    samp1(ib, fx4.z, fy4.z, c0.z, c1.z, c2.z);
    samp1(ib, fx4.w, fy4.w, c0.w, c1.w, c2.w);

    size_t orow = ((size_t)(b * C) * W + y) * W;
    int xo = (t & 127) * 4;
    *(float4*)(out + orow + xo)                     = c0;
    *(float4*)(out + orow + (size_t)W * W + xo)     = c1;
    *(float4*)(out + orow + (size_t)2 * W * W + xo) = c2;
}

// ---------------- launch -----------------------------------------------------
extern "C" void kernel_launch(void* const* d_in, const int* in_sizes, int n_in,
                              void* d_out, int out_size) {
    const float* image = (const float*)d_in[0];
    const float* prim  = (const float*)d_in[1];
    if (in_sizes[0] == B * 2 * W * W) {     // defensive input identification
        prim  = (const float*)d_in[0];
        image = (const float*)d_in[1];
    }

    // gaussian weights on host (double, identical to numpy)
    double sigma = 5.0 * 0.15 + 0.35;       // 1.1
    double p0 = exp(-0.5 * (2.0 / sigma) * (2.0 / sigma));
    double p1 = exp(-0.5 * (1.0 / sigma) * (1.0 / sigma));
    double s  = 2.0 * p0 + 2.0 * p1 + 1.0;
    float w0 = (float)(p0 / s), w1 = (float)(p1 / s), w2 = (float)(1.0 / s);

    static bool attr_done = false;
    if (!attr_done) {
        cudaFuncSetAttribute(k_scan,
                             cudaFuncAttributeMaxDynamicSharedMemorySize,
                             64 * 1024);
        attr_done = true;
    }

    dim3 sg(W / XROWS, B, 2);      // z=0: row role (32x32), z=1: col role (16 used)
    k_scan<<<sg, 512, 64 * 1024>>>(prim, w0, w1, w2);

    k_sample<<<(B * W * W / 4 + 255) / 256, 256>>>(image, (float*)d_out);
}

// round 17
// speedup vs baseline: 1.2472x; 1.2472x over previous
#include <cuda_runtime.h>
#include <math.h>

#define W   512
#define B   32
#define C   3
#define LIM 0.03125f                     // PIX_W * EPS = (2/512)*8
#define DEF_OFF_F (1.0f + 2.0f/511.0f)   // (2 + 4/511)/2
#define FULL 0xffffffffu

// ---------------- scratch (static device arrays; no runtime allocs) --------
__device__ float d_px[(size_t)B * W * W];         // sample x coord in pixels
__device__ float d_py[(size_t)B * W * W];         // sample y coord in pixels

__device__ __forceinline__ int refl(int i) {
    return i < 0 ? -i : (i >= W ? 2 * W - 2 - i : i);
}

// ==== x-channel: fused blur(ch0) + diff->relu->row scan, 8 rows/block =======
#define RROWS 8
__global__ void k_rowscan(const float* __restrict__ pg,
                          float w0, float w1, float w2) {
    __shared__ float ssrc[RROWS + 4][W];   // 24KB
    __shared__ float svb[RROWS][W];        // 16KB
    int b = blockIdx.y;
    int y0 = blockIdx.x * RROWS;
    int tid = threadIdx.x;                 // 256 threads = 8 warps
    const float* src = pg + (size_t)(b * 2) * W * W;   // channel 0

    for (int i = tid; i < (RROWS + 4) * W; i += 256) {
        int r = i >> 9, x = i & 511;
        ssrc[r][x] = src[(size_t)refl(y0 + r - 2) * W + x];
    }
    __syncthreads();

    int warp = tid >> 5, lane = tid & 31;
    int y = y0 + warp;

    #pragma unroll
    for (int k = 0; k < 16; k++) {
        int x = k * 32 + lane;
        svb[warp][x] = w0 * (ssrc[warp][x] + ssrc[warp + 4][x])
                     + w1 * (ssrc[warp + 1][x] + ssrc[warp + 3][x])
                     + w2 * ssrc[warp + 2][x];
    }
    __syncwarp();

    float last31 = 0.f;
    float run = 0.f;
    float* pxo = d_px + ((size_t)b * W + y) * W;
    #pragma unroll
    for (int k = 0; k < 16; k++) {
        int x = k * 32 + lane;
        float bl = w0 * (svb[warp][refl(x - 2)] + svb[warp][refl(x + 2)])
                 + w1 * (svb[warp][refl(x - 1)] + svb[warp][refl(x + 1)])
                 + w2 * svb[warp][x];
        float iden = (2.0f * x - (float)(W - 1)) * (1.0f / (W - 1));
        float s = bl + iden + DEF_OFF_F;
        float sprev = __shfl_up_sync(FULL, s, 1);
        if (lane == 0) sprev = last31;
        float a = fmaxf(s - sprev, 0.f);
        last31 = __shfl_sync(FULL, s, 31);

        float v = a;
        #pragma unroll
        for (int o = 1; o < 32; o <<= 1) {
            float n = __shfl_up_sync(FULL, v, o);
            if (lane >= o) v += n;
        }
        float sx2 = run + v;
        run += __shfl_sync(FULL, v, 31);

        float pgv = sx2 - DEF_OFF_F - iden;
        pgv = fminf(fmaxf(pgv, -LIM), LIM);
        float gx = fminf(fmaxf(pgv + iden, -1.f), 1.f);
        pxo[x] = (gx + 1.f) * 0.5f * (float)(W - 1);
    }
}

// ==== y-channel: fused blur(ch1) + tiled column scan, writes d_py ===========
#define SEG 32
#define NSEG (W / SEG)
__global__ void k_colscan(const float* __restrict__ pg,
                          float w0, float w1, float w2) {
    extern __shared__ float hb[];          // [W][32] = 64KB
    __shared__ float segsum[NSEG][33];
    int tx = threadIdx.x;                  // 0..31 column in tile
    int ty = threadIdx.y;                  // 0..15 segment
    int x = blockIdx.x * 32 + tx;
    int b = blockIdx.y;
    const float* src = pg + (size_t)(b * 2 + 1) * W * W;   // channel 1

    int xm2 = refl(x - 2), xm1 = refl(x - 1), xp1 = refl(x + 1), xp2 = refl(x + 2);

    // phase 1: horizontal blur for this column, rows ty*32 .. ty*32+31
    int y0 = ty * SEG;
    #pragma unroll 4
    for (int r = 0; r < SEG; r++) {
        const float* row = src + (size_t)(y0 + r) * W;
        hb[(y0 + r) * 32 + tx] =
            w0 * (__ldg(row + xm2) + __ldg(row + xp2))
          + w1 * (__ldg(row + xm1) + __ldg(row + xp1))
          + w2 * __ldg(row + x);
    }
    __syncthreads();

    // phase 2: serial scan with rolling vertical-blur window
    float h0 = hb[refl(y0 - 2) * 32 + tx];
    float h1 = hb[refl(y0 - 1) * 32 + tx];
    float h2 = hb[y0 * 32 + tx];
    float h3 = hb[(y0 + 1) * 32 + tx];
    float h4 = hb[refl(y0 + 2) * 32 + tx];

    float prev = 0.f;
    if (ty > 0) {   // s at row y0-1
        float g0 = hb[refl(y0 - 3) * 32 + tx];
        float vbp = w0 * (g0 + h3) + w1 * (h0 + h2) + w2 * h1;
        float idenp = (2.0f * (y0 - 1) - (float)(W - 1)) * (1.0f / (W - 1));
        prev = vbp + idenp + DEF_OFF_F;
    }

    float vals[SEG];
    float run = 0.f;
    #pragma unroll
    for (int r = 0; r < SEG; r++) {
        int y = y0 + r;
        float vb = w0 * (h0 + h4) + w1 * (h1 + h3) + w2 * h2;
        float iden = (2.0f * y - (float)(W - 1)) * (1.0f / (W - 1));
        float s = vb + iden + DEF_OFF_F;
        float a = fmaxf(s - prev, 0.f);
        prev = s;
        run += a;
        vals[r] = run;
        h0 = h1; h1 = h2; h2 = h3; h3 = h4;
        h4 = hb[refl(y + 3) * 32 + tx];
    }
    segsum[ty][tx] = run;
    __syncthreads();

    if (ty == 0) {
        float off = 0.f;
        #pragma unroll
        for (int k = 0; k < NSEG; k++) {
            float t = segsum[k][tx];
            segsum[k][tx] = off;
            off += t;
        }
    }
    __syncthreads();
    float offset = segsum[ty][tx];

    float* py = d_py + (size_t)b * W * W + x;
    #pragma unroll
    for (int r = 0; r < SEG; r++) {
        int y = y0 + r;
        float iden = (2.0f * y - (float)(W - 1)) * (1.0f / (W - 1));
        float sy2 = vals[r] + offset;
        float pgv = sy2 - DEF_OFF_F - iden;
        pgv = fminf(fmaxf(pgv, -LIM), LIM);
        float gy = fminf(fmaxf(pgv + iden, -1.f), 1.f);
        py[(size_t)y * W] = (gy + 1.f) * 0.5f * (float)(W - 1);
    }
}

// ==== bilinear grid sample, 1 pixel / thread (lane-consecutive x) ============
// Grid coords are clipped to [-1,1] upstream => fx,fy in [0,511]:
// no validity predicates needed; only x1/y1 clamp (their weight is 0 there).
__global__ void k_sample(const float* __restrict__ img, float* __restrict__ out) {
    int idx = blockIdx.x * blockDim.x + threadIdx.x;   // b*W*W + y*W + x
    if (idx >= B * W * W) return;
    int b = idx >> 18;
    int yx = idx & (W * W - 1);

    float fx = __ldg(d_px + idx);
    float fy = __ldg(d_py + idx);

    float x0f = floorf(fx), y0f = floorf(fy);
    int x0 = (int)x0f, y0 = (int)y0f;                  // in [0,511]
    int x1 = min(x0 + 1, W - 1), y1 = min(y0 + 1, W - 1);
    float wx1 = fx - x0f, wx0 = 1.f - wx1;
    float wy1 = fy - y0f, wy0 = 1.f - wy1;

    const float* ib = img + (size_t)b * C * W * W;
    int o00 = y0 * W + x0, o10 = y0 * W + x1;
    int o01 = y1 * W + x0, o11 = y1 * W + x1;

    float* ob = out + (size_t)b * C * W * W + yx;
    #pragma unroll
    for (int c = 0; c < C; c++) {
        const float* ic = ib + c * W * W;
        float top = wx0 * __ldg(ic + o00) + wx1 * __ldg(ic + o10);
        float bot = wx0 * __ldg(ic + o01) + wx1 * __ldg(ic + o11);
        ob[c * W * W] = wy0 * top + wy1 * bot;
    }
}

// ---------------- launch -----------------------------------------------------
extern "C" void kernel_launch(void* const* d_in, const int* in_sizes, int n_in,
                              void* d_out, int out_size) {
    const float* image = (const float*)d_in[0];
    const float* prim  = (const float*)d_in[1];
    if (in_sizes[0] == B * 2 * W * W) {     // defensive input identification
        prim  = (const float*)d_in[0];
        image = (const float*)d_in[1];
    }

    // gaussian weights on host (double, identical to numpy)
    double sigma = 5.0 * 0.15 + 0.35;       // 1.1
    double p0 = exp(-0.5 * (2.0 / sigma) * (2.0 / sigma));
    double p1 = exp(-0.5 * (1.0 / sigma) * (1.0 / sigma));
    double s  = 2.0 * p0 + 2.0 * p1 + 1.0;
    float w0 = (float)(p0 / s), w1 = (float)(p1 / s), w2 = (float)(1.0 / s);

    static bool attr_done = false;
    if (!attr_done) {
        cudaFuncSetAttribute(k_colscan,
                             cudaFuncAttributeMaxDynamicSharedMemorySize,
                             W * 32 * (int)sizeof(float));
        attr_done = true;
    }

    dim3 rg(W / RROWS, B);
    k_rowscan<<<rg, 256>>>(prim, w0, w1, w2);

    dim3 cb(32, NSEG);
    dim3 cg(W / 32, B);
    k_colscan<<<cg, cb, W * 32 * sizeof(float)>>>(prim, w0, w1, w2);

    k_sample<<<(B * W * W + 255) / 256, 256>>>(image, (float*)d_out);
}